// round 6
// baseline (speedup 1.0000x reference)
#include <cuda_runtime.h>
#include <cuda_bf16.h>

#define N_USER 50000
#define N_ITEM 100000
#define NTOT   150000
#define DEMB   64
#define NNZT   2400000
#define BSZ    4096
#define NLAYER 3
#define NEG_SLOPE 0.2f

// ------------------- static device scratch -------------------
__device__ __align__(256) float g_Elay[NLAYER][NTOT * DEMB];  // unnormalized layer outputs
__device__ __align__(256) float g_inorm[NLAYER][NTOT];        // 1/max(norm,eps)
__device__ __align__(256) float g_AM[NTOT * 2 * DEMB];        // [a | m] GEMM operand
__device__ int  g_cnt[NTOT + 1];
__device__ int  g_off[NTOT + 1];
__device__ int  g_cur[NTOT + 1];
__device__ int2 g_cv[NNZT];                                   // packed (col, val-bits)
__device__ int  g_part[256];

// packed f32x2 helpers (Blackwell FFMA2 — PTX-only)
__device__ __forceinline__ void unpack2(unsigned long long v, float& x, float& y) {
    asm("mov.b64 {%0, %1}, %2;" : "=f"(x), "=f"(y) : "l"(v));
}
__device__ __forceinline__ void fma2(unsigned long long& d, unsigned long long a,
                                     unsigned long long b) {
    asm("fma.rn.f32x2 %0, %1, %2, %0;" : "+l"(d) : "l"(a), "l"(b));
}

// ------------------- CSR build -------------------
__global__ void k_count(const int* __restrict__ rows) {
    int e = blockIdx.x * blockDim.x + threadIdx.x;
    if (e < NNZT) atomicAdd(&g_cnt[rows[e]], 1);
}

#define SCAN_NBLK 147

__global__ void k_scan1() {
    __shared__ int s[1024];
    int t = threadIdx.x;
    int i = blockIdx.x * 1024 + t;
    int x = (i <= NTOT) ? g_cnt[i] : 0;
    s[t] = x;
    __syncthreads();
    for (int d = 512; d > 0; d >>= 1) {
        if (t < d) s[t] += s[t + d];
        __syncthreads();
    }
    if (t == 0) g_part[blockIdx.x] = s[0];
}

__global__ void k_scan2() {
    if (threadIdx.x == 0 && blockIdx.x == 0) {
        int run = 0;
        for (int b = 0; b < SCAN_NBLK; b++) {
            int v = g_part[b];
            g_part[b] = run;
            run += v;
        }
    }
}

__global__ void k_scan3() {
    __shared__ int s[1024];
    int t = threadIdx.x;
    int i = blockIdx.x * 1024 + t;
    int x = (i <= NTOT) ? g_cnt[i] : 0;
    s[t] = x;
    __syncthreads();
    for (int d = 1; d < 1024; d <<= 1) {
        int v = (t >= d) ? s[t - d] : 0;
        __syncthreads();
        s[t] += v;
        __syncthreads();
    }
    int excl = g_part[blockIdx.x] + s[t] - x;
    if (i <= NTOT) {
        g_off[i] = excl;
        g_cur[i] = excl;
    }
}

__global__ void k_fill(const int* __restrict__ rows, const int* __restrict__ cols,
                       const float* __restrict__ vals) {
    int e = blockIdx.x * blockDim.x + threadIdx.x;
    if (e < NNZT) {
        int r = rows[e];
        int p = atomicAdd(&g_cur[r], 1);
        g_cv[p] = make_int2(cols[e], __float_as_int(vals[e]));
    }
}

// ------------------- SpMM gather (half-warp float4): writes AM = [LE+E | LE*E] -------------------
#define SW 16  // warps per block

__global__ __launch_bounds__(512) void k_spmm(int layer,
                                              const float* __restrict__ ue,
                                              const float* __restrict__ ie) {
    const float* __restrict__ Eprev = (layer == 0) ? (const float*)nullptr : g_Elay[layer - 1];
    int tid = threadIdx.x;
    int warp = tid >> 5, lane = tid & 31;
    int half = lane >> 4, hl = lane & 15;
    int ngroups = (NTOT + SW - 1) / SW;

    for (int g = blockIdx.x; g < ngroups; g += gridDim.x) {
        int r = g * SW + warp;
        if (r >= NTOT) continue;
        int s = g_off[r], e2 = g_off[r + 1];
        float4 acc = make_float4(0.f, 0.f, 0.f, 0.f);
        for (int base = s; base < e2; base += 32) {
            int2 cv = make_int2(0, 0);
            if (base + lane < e2) cv = g_cv[base + lane];
            int cnt = min(32, e2 - base);
            int cnt2 = (cnt + 1) & ~1;
#pragma unroll 4
            for (int i = 0; i < cnt2; i += 2) {
                int src = i + half;  // low half: edge i, high half: edge i+1
                int cc = __shfl_sync(0xffffffffu, cv.x, src);
                float vv = __int_as_float(__shfl_sync(0xffffffffu, cv.y, src));
                const float* rowp;
                if (layer == 0)
                    rowp = (cc < N_USER) ? (ue + (size_t)cc * DEMB)
                                         : (ie + (size_t)(cc - N_USER) * DEMB);
                else
                    rowp = Eprev + (size_t)cc * DEMB;
                float4 x = *(const float4*)(rowp + hl * 4);
                acc.x = fmaf(vv, x.x, acc.x);
                acc.y = fmaf(vv, x.y, acc.y);
                acc.z = fmaf(vv, x.z, acc.z);
                acc.w = fmaf(vv, x.w, acc.w);
            }
        }
        // combine the two half-warp edge-subsets (same dims in both halves)
        acc.x += __shfl_xor_sync(0xffffffffu, acc.x, 16);
        acc.y += __shfl_xor_sync(0xffffffffu, acc.y, 16);
        acc.z += __shfl_xor_sync(0xffffffffu, acc.z, 16);
        acc.w += __shfl_xor_sync(0xffffffffu, acc.w, 16);

        const float* rp0;
        if (layer == 0)
            rp0 = (r < N_USER) ? (ue + (size_t)r * DEMB)
                               : (ie + (size_t)(r - N_USER) * DEMB);
        else
            rp0 = Eprev + (size_t)r * DEMB;
        float4 e0 = *(const float4*)(rp0 + hl * 4);
        if (half == 0) {
            *(float4*)&g_AM[(size_t)r * 128 + hl * 4] =
                make_float4(acc.x + e0.x, acc.y + e0.y, acc.z + e0.z, acc.w + e0.w);
        } else {
            *(float4*)&g_AM[(size_t)r * 128 + DEMB + hl * 4] =
                make_float4(acc.x * e0.x, acc.y * e0.y, acc.z * e0.z, acc.w * e0.w);
        }
    }
}

// ------------------- tiled GEMM (FFMA2, zero-mov inner loop) -------------------
#define BM 128
#define BN 64
#define BK 16
#define PADA 4
#define PADB 4

__global__ __launch_bounds__(128) void k_gemm(int layer,
                                              const float* __restrict__ W1l,
                                              const float* __restrict__ W2l,
                                              const float* __restrict__ b1l,
                                              const float* __restrict__ b2l) {
    __shared__ __align__(16) float sA[BK][BM + PADA];
    __shared__ __align__(16) float sBd[BK][2 * BN + PADB];  // pre-duplicated (b,b)
    __shared__ float sBias[BN];

    float* __restrict__ Eout = g_Elay[layer];
    float* __restrict__ inorm = g_inorm[layer];

    int tid = threadIdx.x;
    int tx = tid & 7;    // 8 col-groups of 8
    int ty = tid >> 3;   // 16 row-groups of 8
    int m0 = blockIdx.x * BM;

    if (tid < BN) sBias[tid] = b1l[tid] + b2l[tid];

    unsigned long long acc2[4][8];  // [row-pair][col]; each = 2 fp32 accumulators
#pragma unroll
    for (int i = 0; i < 4; i++)
#pragma unroll
        for (int j = 0; j < 8; j++) acc2[i][j] = 0ull;

    for (int k0 = 0; k0 < 2 * DEMB; k0 += BK) {
        // A tile: rows m0..m0+127, cols k0..k0+15 -> sA[k][m] (transposed)
#pragma unroll
        for (int i = 0; i < 4; i++) {
            int idx = tid + i * 128;        // float4 index 0..511
            int m = idx >> 2;
            int kq = (idx & 3) * 4;
            float4 v = make_float4(0.f, 0.f, 0.f, 0.f);
            int gr = m0 + m;
            if (gr < NTOT) v = *(const float4*)&g_AM[(size_t)gr * 128 + k0 + kq];
            sA[kq + 0][m] = v.x;
            sA[kq + 1][m] = v.y;
            sA[kq + 2][m] = v.z;
            sA[kq + 3][m] = v.w;
        }
        // B tile, duplicated: sBd[k][2j..2j+1] = (b, b)
#pragma unroll
        for (int i = 0; i < 2; i++) {
            int idx = tid + i * 128;        // float4 index 0..255
            int kr = idx >> 4;
            int cq = (idx & 15) * 4;
            int gk = k0 + kr;
            const float* Wsrc = (gk < DEMB) ? (W1l + gk * DEMB) : (W2l + (gk - DEMB) * DEMB);
            float4 v = *(const float4*)&Wsrc[cq];
            *(float4*)&sBd[kr][2 * cq] = make_float4(v.x, v.x, v.y, v.y);
            *(float4*)&sBd[kr][2 * cq + 4] = make_float4(v.z, v.z, v.w, v.w);
        }
        __syncthreads();
#pragma unroll
        for (int kk = 0; kk < BK; kk++) {
            unsigned long long au[4], bd[8];
            ulonglong2 t0 = *(const ulonglong2*)&sA[kk][ty * 8];
            ulonglong2 t1 = *(const ulonglong2*)&sA[kk][ty * 8 + 4];
            au[0] = t0.x; au[1] = t0.y; au[2] = t1.x; au[3] = t1.y;
            ulonglong2 u0 = *(const ulonglong2*)&sBd[kk][tx * 16];
            ulonglong2 u1 = *(const ulonglong2*)&sBd[kk][tx * 16 + 4];
            ulonglong2 u2 = *(const ulonglong2*)&sBd[kk][tx * 16 + 8];
            ulonglong2 u3 = *(const ulonglong2*)&sBd[kk][tx * 16 + 12];
            bd[0] = u0.x; bd[1] = u0.y; bd[2] = u1.x; bd[3] = u1.y;
            bd[4] = u2.x; bd[5] = u2.y; bd[6] = u3.x; bd[7] = u3.y;
#pragma unroll
            for (int ip = 0; ip < 4; ip++)
#pragma unroll
                for (int j = 0; j < 8; j++)
                    fma2(acc2[ip][j], au[ip], bd[j]);
        }
        __syncthreads();
    }

    float bias[8];
    *(float4*)&bias[0] = *(float4*)&sBias[tx * 8];
    *(float4*)&bias[4] = *(float4*)&sBias[tx * 8 + 4];

#pragma unroll
    for (int ip = 0; ip < 4; ip++) {
        float h0[8], h1[8];
        float ss0 = 0.f, ss1 = 0.f;
#pragma unroll
        for (int j = 0; j < 8; j++) {
            float v0, v1;
            unpack2(acc2[ip][j], v0, v1);
            v0 += bias[j];
            v1 += bias[j];
            v0 = v0 > 0.f ? v0 : NEG_SLOPE * v0;
            v1 = v1 > 0.f ? v1 : NEG_SLOPE * v1;
            h0[j] = v0;
            h1[j] = v1;
            ss0 = fmaf(v0, v0, ss0);
            ss1 = fmaf(v1, v1, ss1);
        }
        ss0 += __shfl_xor_sync(0xffffffffu, ss0, 1);
        ss0 += __shfl_xor_sync(0xffffffffu, ss0, 2);
        ss0 += __shfl_xor_sync(0xffffffffu, ss0, 4);
        ss1 += __shfl_xor_sync(0xffffffffu, ss1, 1);
        ss1 += __shfl_xor_sync(0xffffffffu, ss1, 2);
        ss1 += __shfl_xor_sync(0xffffffffu, ss1, 4);
        int r0 = m0 + ty * 8 + 2 * ip;
        int r1 = r0 + 1;
        if (r0 < NTOT) {
            *(float4*)&Eout[(size_t)r0 * DEMB + tx * 8] = *(float4*)&h0[0];
            *(float4*)&Eout[(size_t)r0 * DEMB + tx * 8 + 4] = *(float4*)&h0[4];
            if (tx == 0) inorm[r0] = 1.0f / fmaxf(sqrtf(ss0), 1e-12f);
        }
        if (r1 < NTOT) {
            *(float4*)&Eout[(size_t)r1 * DEMB + tx * 8] = *(float4*)&h1[0];
            *(float4*)&Eout[(size_t)r1 * DEMB + tx * 8 + 4] = *(float4*)&h1[4];
            if (tx == 0) inorm[r1] = 1.0f / fmaxf(sqrtf(ss1), 1e-12f);
        }
    }
}

// ------------------- final gather -------------------
__global__ void k_gather(const int* __restrict__ users, const int* __restrict__ pos,
                         const int* __restrict__ neg, const float* __restrict__ ue,
                         const float* __restrict__ ie, float* __restrict__ out) {
    int b = blockIdx.x;
    int grp = b >> 12;
    int i = b & (BSZ - 1);
    int node;
    if (grp == 0) node = users[i] - 1;
    else if (grp == 1) node = N_USER + pos[i] - 1;
    else node = N_USER + neg[i] - 1;

    int j = threadIdx.x;  // 0..255
    int l = j >> 6, jj = j & 63;
    float v;
    if (l == 0) {
        v = (node < N_USER) ? ue[(size_t)node * DEMB + jj]
                            : ie[(size_t)(node - N_USER) * DEMB + jj];
    } else {
        v = g_Elay[l - 1][(size_t)node * DEMB + jj] * g_inorm[l - 1][node];
    }
    out[(size_t)b * 256 + j] = v;
}

// ------------------- launch -------------------
extern "C" void kernel_launch(void* const* d_in, const int* in_sizes, int n_in,
                              void* d_out, int out_size) {
    const float* ue = (const float*)d_in[0];
    const float* ie = (const float*)d_in[1];
    const float* ev = (const float*)d_in[2];
    const float* W1 = (const float*)d_in[3];
    const float* b1 = (const float*)d_in[4];
    const float* W2 = (const float*)d_in[5];
    const float* b2 = (const float*)d_in[6];
    const int* eidx = (const int*)d_in[7];
    const int* users = (const int*)d_in[8];
    const int* pos = (const int*)d_in[9];
    const int* neg = (const int*)d_in[10];
    float* out = (float*)d_out;

    const int* rows = eidx;
    const int* cols = eidx + NNZT;

    static void* p_cnt = nullptr;
    if (!p_cnt) cudaGetSymbolAddress(&p_cnt, g_cnt);

    cudaMemsetAsync(p_cnt, 0, (NTOT + 1) * sizeof(int));
    k_count<<<(NNZT + 255) / 256, 256>>>(rows);
    k_scan1<<<SCAN_NBLK, 1024>>>();
    k_scan2<<<1, 32>>>();
    k_scan3<<<SCAN_NBLK, 1024>>>();
    k_fill<<<(NNZT + 255) / 256, 256>>>(rows, cols, ev);

    for (int l = 0; l < NLAYER; l++) {
        k_spmm<<<592, 512>>>(l, ue, ie);
        k_gemm<<<(NTOT + BM - 1) / BM, 128>>>(l, W1 + l * DEMB * DEMB, W2 + l * DEMB * DEMB,
                                              b1 + l * DEMB, b2 + l * DEMB);
    }
    k_gather<<<3 * BSZ, 256>>>(users, pos, neg, ue, ie, out);
}

// round 7
// speedup vs baseline: 1.7287x; 1.7287x over previous
#include <cuda_runtime.h>
#include <cuda_bf16.h>

#define N_USER 50000
#define N_ITEM 100000
#define NTOT   150000
#define DEMB   64
#define NNZT   2400000
#define BSZ    4096
#define NLAYER 3
#define NEG_SLOPE 0.2f

// ------------------- static device scratch -------------------
__device__ __align__(256) float g_Elay[NLAYER][NTOT * DEMB];  // unnormalized layer outputs
__device__ __align__(256) float g_inorm[NLAYER][NTOT];        // 1/max(norm,eps)
__device__ __align__(256) float g_AM[NTOT * 2 * DEMB];        // [a | m] GEMM operand
__device__ int  g_cnt[NTOT + 1];
__device__ int  g_off[NTOT + 1];
__device__ int  g_cur[NTOT + 1];
__device__ int2 g_cv[NNZT];                                   // packed (col, val-bits)
__device__ int  g_part[256];

// packed f32x2 helpers (Blackwell FFMA2 — PTX-only)
__device__ __forceinline__ unsigned long long pack2(float x, float y) {
    unsigned long long r;
    asm("mov.b64 %0, {%1, %2};" : "=l"(r) : "f"(x), "f"(y));
    return r;
}
__device__ __forceinline__ void unpack2(unsigned long long v, float& x, float& y) {
    asm("mov.b64 {%0, %1}, %2;" : "=f"(x), "=f"(y) : "l"(v));
}
__device__ __forceinline__ void fma2(unsigned long long& d, unsigned long long a,
                                     unsigned long long b) {
    asm("fma.rn.f32x2 %0, %1, %2, %0;" : "+l"(d) : "l"(a), "l"(b));
}

// ------------------- CSR build -------------------
__global__ void k_count(const int* __restrict__ rows) {
    int e = blockIdx.x * blockDim.x + threadIdx.x;
    if (e < NNZT) atomicAdd(&g_cnt[rows[e]], 1);
}

#define SCAN_NBLK 147

__global__ void k_scan1() {
    __shared__ int s[1024];
    int t = threadIdx.x;
    int i = blockIdx.x * 1024 + t;
    int x = (i <= NTOT) ? g_cnt[i] : 0;
    s[t] = x;
    __syncthreads();
    for (int d = 512; d > 0; d >>= 1) {
        if (t < d) s[t] += s[t + d];
        __syncthreads();
    }
    if (t == 0) g_part[blockIdx.x] = s[0];
}

__global__ void k_scan2() {
    if (threadIdx.x == 0 && blockIdx.x == 0) {
        int run = 0;
        for (int b = 0; b < SCAN_NBLK; b++) {
            int v = g_part[b];
            g_part[b] = run;
            run += v;
        }
    }
}

__global__ void k_scan3() {
    __shared__ int s[1024];
    int t = threadIdx.x;
    int i = blockIdx.x * 1024 + t;
    int x = (i <= NTOT) ? g_cnt[i] : 0;
    s[t] = x;
    __syncthreads();
    for (int d = 1; d < 1024; d <<= 1) {
        int v = (t >= d) ? s[t - d] : 0;
        __syncthreads();
        s[t] += v;
        __syncthreads();
    }
    int excl = g_part[blockIdx.x] + s[t] - x;
    if (i <= NTOT) {
        g_off[i] = excl;
        g_cur[i] = excl;
    }
}

__global__ void k_fill(const int* __restrict__ rows, const int* __restrict__ cols,
                       const float* __restrict__ vals) {
    int e = blockIdx.x * blockDim.x + threadIdx.x;
    if (e < NNZT) {
        int r = rows[e];
        int p = atomicAdd(&g_cur[r], 1);
        g_cv[p] = make_int2(cols[e], __float_as_int(vals[e]));
    }
}

// ------------------- SpMM gather (full-warp float2, MLP=8): AM = [LE+E | LE*E] -------------------
#define SW 16  // warps per block

__global__ __launch_bounds__(512) void k_spmm(int layer,
                                              const float* __restrict__ ue,
                                              const float* __restrict__ ie) {
    const float* __restrict__ Eprev = (layer == 0) ? (const float*)nullptr : g_Elay[layer - 1];
    int tid = threadIdx.x;
    int warp = tid >> 5, lane = tid & 31;
    int ngroups = (NTOT + SW - 1) / SW;

    for (int g = blockIdx.x; g < ngroups; g += gridDim.x) {
        int r = g * SW + warp;
        if (r >= NTOT) continue;
        int s = g_off[r], e2 = g_off[r + 1];
        float2 acc = make_float2(0.f, 0.f);
        for (int base = s; base < e2; base += 32) {
            int2 cv = make_int2(0, 0);
            if (base + lane < e2) cv = g_cv[base + lane];
            int cnt = min(32, e2 - base);
            int cnt8 = (cnt + 7) & ~7;
            for (int i = 0; i < cnt8; i += 8) {
#pragma unroll
                for (int u = 0; u < 8; u++) {
                    int cc = __shfl_sync(0xffffffffu, cv.x, i + u);
                    float vv = __int_as_float(__shfl_sync(0xffffffffu, cv.y, i + u));
                    const float* rowp;
                    if (layer == 0)
                        rowp = (cc < N_USER) ? (ue + (size_t)cc * DEMB)
                                             : (ie + (size_t)(cc - N_USER) * DEMB);
                    else
                        rowp = Eprev + (size_t)cc * DEMB;
                    float2 x = *(const float2*)(rowp + lane * 2);
                    acc.x = fmaf(vv, x.x, acc.x);
                    acc.y = fmaf(vv, x.y, acc.y);
                }
            }
        }
        const float* rp0;
        if (layer == 0)
            rp0 = (r < N_USER) ? (ue + (size_t)r * DEMB)
                               : (ie + (size_t)(r - N_USER) * DEMB);
        else
            rp0 = Eprev + (size_t)r * DEMB;
        float2 e0 = *(const float2*)(rp0 + lane * 2);
        *(float2*)&g_AM[(size_t)r * 128 + lane * 2] =
            make_float2(acc.x + e0.x, acc.y + e0.y);
        *(float2*)&g_AM[(size_t)r * 128 + DEMB + lane * 2] =
            make_float2(acc.x * e0.x, acc.y * e0.y);
    }
}

// ------------------- tiled GEMM (FFMA2, round-4 layout): leaky(AM @ [W1;W2] + b) + inv-norm -------------------
#define BM 128
#define BN 64
#define BK 16
#define PADA 4
#define PADB 4

__global__ __launch_bounds__(128) void k_gemm(int layer,
                                              const float* __restrict__ W1l,
                                              const float* __restrict__ W2l,
                                              const float* __restrict__ b1l,
                                              const float* __restrict__ b2l) {
    __shared__ __align__(16) float sA[BK][BM + PADA];
    __shared__ __align__(16) float sB[BK][BN + PADB];
    __shared__ float sBias[BN];

    float* __restrict__ Eout = g_Elay[layer];
    float* __restrict__ inorm = g_inorm[layer];

    int tid = threadIdx.x;
    int tx = tid & 7;    // 8 col-groups of 8
    int ty = tid >> 3;   // 16 row-groups of 8
    int m0 = blockIdx.x * BM;

    if (tid < BN) sBias[tid] = b1l[tid] + b2l[tid];

    unsigned long long acc2[8][4];  // [i][j-pair], each holds 2 fp32 accumulators
#pragma unroll
    for (int i = 0; i < 8; i++)
#pragma unroll
        for (int j = 0; j < 4; j++) acc2[i][j] = 0ull;

    for (int k0 = 0; k0 < 2 * DEMB; k0 += BK) {
        // A tile: rows m0..m0+127, cols k0..k0+15 -> sA[k][m] (transposed)
#pragma unroll
        for (int i = 0; i < 4; i++) {
            int idx = tid + i * 128;        // float4 index 0..511
            int m = idx >> 2;
            int kq = (idx & 3) * 4;
            float4 v = make_float4(0.f, 0.f, 0.f, 0.f);
            int gr = m0 + m;
            if (gr < NTOT) v = *(const float4*)&g_AM[(size_t)gr * 128 + k0 + kq];
            sA[kq + 0][m] = v.x;
            sA[kq + 1][m] = v.y;
            sA[kq + 2][m] = v.z;
            sA[kq + 3][m] = v.w;
        }
        // B tile: Wcat rows k0..k0+15 (W1 rows then W2 rows), cols 0..63
#pragma unroll
        for (int i = 0; i < 2; i++) {
            int idx = tid + i * 128;        // float4 index 0..255
            int kr = idx >> 4;
            int cq = (idx & 15) * 4;
            int gk = k0 + kr;
            const float* Wsrc = (gk < DEMB) ? (W1l + gk * DEMB) : (W2l + (gk - DEMB) * DEMB);
            *(float4*)&sB[kr][cq] = *(const float4*)&Wsrc[cq];
        }
        __syncthreads();
#pragma unroll
        for (int kk = 0; kk < BK; kk++) {
            float a[8], b[8];
            *(float4*)&a[0] = *(float4*)&sA[kk][ty * 8];
            *(float4*)&a[4] = *(float4*)&sA[kk][ty * 8 + 4];
            *(float4*)&b[0] = *(float4*)&sB[kk][tx * 8];
            *(float4*)&b[4] = *(float4*)&sB[kk][tx * 8 + 4];
            unsigned long long ap[8], bp[4];
#pragma unroll
            for (int i = 0; i < 8; i++) ap[i] = pack2(a[i], a[i]);
#pragma unroll
            for (int j = 0; j < 4; j++) bp[j] = pack2(b[2 * j], b[2 * j + 1]);
#pragma unroll
            for (int i = 0; i < 8; i++)
#pragma unroll
                for (int j = 0; j < 4; j++)
                    fma2(acc2[i][j], ap[i], bp[j]);
        }
        __syncthreads();
    }

    float bias[8];
    *(float4*)&bias[0] = *(float4*)&sBias[tx * 8];
    *(float4*)&bias[4] = *(float4*)&sBias[tx * 8 + 4];

#pragma unroll
    for (int i = 0; i < 8; i++) {
        int r = m0 + ty * 8 + i;
        float h[8];
        float ss = 0.f;
#pragma unroll
        for (int j = 0; j < 4; j++) {
            float v0, v1;
            unpack2(acc2[i][j], v0, v1);
            v0 += bias[2 * j];
            v1 += bias[2 * j + 1];
            v0 = v0 > 0.f ? v0 : NEG_SLOPE * v0;
            v1 = v1 > 0.f ? v1 : NEG_SLOPE * v1;
            h[2 * j] = v0;
            h[2 * j + 1] = v1;
            ss = fmaf(v0, v0, ss);
            ss = fmaf(v1, v1, ss);
        }
        ss += __shfl_xor_sync(0xffffffffu, ss, 1);
        ss += __shfl_xor_sync(0xffffffffu, ss, 2);
        ss += __shfl_xor_sync(0xffffffffu, ss, 4);
        if (r < NTOT) {
            *(float4*)&Eout[(size_t)r * DEMB + tx * 8] = *(float4*)&h[0];
            *(float4*)&Eout[(size_t)r * DEMB + tx * 8 + 4] = *(float4*)&h[4];
            if (tx == 0) inorm[r] = 1.0f / fmaxf(sqrtf(ss), 1e-12f);
        }
    }
}

// ------------------- final gather -------------------
__global__ void k_gather(const int* __restrict__ users, const int* __restrict__ pos,
                         const int* __restrict__ neg, const float* __restrict__ ue,
                         const float* __restrict__ ie, float* __restrict__ out) {
    int b = blockIdx.x;
    int grp = b >> 12;
    int i = b & (BSZ - 1);
    int node;
    if (grp == 0) node = users[i] - 1;
    else if (grp == 1) node = N_USER + pos[i] - 1;
    else node = N_USER + neg[i] - 1;

    int j = threadIdx.x;  // 0..255
    int l = j >> 6, jj = j & 63;
    float v;
    if (l == 0) {
        v = (node < N_USER) ? ue[(size_t)node * DEMB + jj]
                            : ie[(size_t)(node - N_USER) * DEMB + jj];
    } else {
        v = g_Elay[l - 1][(size_t)node * DEMB + jj] * g_inorm[l - 1][node];
    }
    out[(size_t)b * 256 + j] = v;
}

// ------------------- launch -------------------
extern "C" void kernel_launch(void* const* d_in, const int* in_sizes, int n_in,
                              void* d_out, int out_size) {
    const float* ue = (const float*)d_in[0];
    const float* ie = (const float*)d_in[1];
    const float* ev = (const float*)d_in[2];
    const float* W1 = (const float*)d_in[3];
    const float* b1 = (const float*)d_in[4];
    const float* W2 = (const float*)d_in[5];
    const float* b2 = (const float*)d_in[6];
    const int* eidx = (const int*)d_in[7];
    const int* users = (const int*)d_in[8];
    const int* pos = (const int*)d_in[9];
    const int* neg = (const int*)d_in[10];
    float* out = (float*)d_out;

    const int* rows = eidx;
    const int* cols = eidx + NNZT;

    static void* p_cnt = nullptr;
    if (!p_cnt) cudaGetSymbolAddress(&p_cnt, g_cnt);

    cudaMemsetAsync(p_cnt, 0, (NTOT + 1) * sizeof(int));
    k_count<<<(NNZT + 255) / 256, 256>>>(rows);
    k_scan1<<<SCAN_NBLK, 1024>>>();
    k_scan2<<<1, 32>>>();
    k_scan3<<<SCAN_NBLK, 1024>>>();
    k_fill<<<(NNZT + 255) / 256, 256>>>(rows, cols, ev);

    for (int l = 0; l < NLAYER; l++) {
        k_spmm<<<592, 512>>>(l, ue, ie);
        k_gemm<<<(NTOT + BM - 1) / BM, 128>>>(l, W1 + l * DEMB * DEMB, W2 + l * DEMB * DEMB,
                                              b1 + l * DEMB, b2 + l * DEMB);
    }
    k_gather<<<3 * BSZ, 256>>>(users, pos, neg, ue, ie, out);
}

// round 8
// speedup vs baseline: 1.7686x; 1.0231x over previous
#include <cuda_runtime.h>
#include <cuda_fp16.h>

#define N_USER 50000
#define N_ITEM 100000
#define NTOT   150000
#define DEMB   64
#define NNZT   2400000
#define BSZ    4096
#define NLAYER 3
#define NEG_SLOPE 0.2f

// ------------------- static device scratch -------------------
__device__ __align__(256) float  g_Elay[NLAYER][NTOT * DEMB];  // unnormalized fp32 layer outputs
__device__ __align__(256) __half g_E0h[NTOT * DEMB];           // fp16 concat(ue,ie) gather table
__device__ __align__(256) __half g_Elayh[2][NTOT * DEMB];      // fp16 shadow of layers 0,1
__device__ __align__(256) float  g_inorm[NLAYER][NTOT];        // 1/max(norm,eps)
__device__ __align__(256) float  g_AM[NTOT * 2 * DEMB];        // [a | m] GEMM operand
__device__ int  g_cnt[NTOT + 1];
__device__ int  g_off[NTOT + 1];
__device__ int  g_cur[NTOT + 1];
__device__ int2 g_cv[NNZT];                                    // packed (col, val-bits)
__device__ int  g_part[256];

// packed f32x2 helpers (Blackwell FFMA2 — PTX-only)
__device__ __forceinline__ unsigned long long pack2(float x, float y) {
    unsigned long long r;
    asm("mov.b64 %0, {%1, %2};" : "=l"(r) : "f"(x), "f"(y));
    return r;
}
__device__ __forceinline__ void unpack2(unsigned long long v, float& x, float& y) {
    asm("mov.b64 {%0, %1}, %2;" : "=f"(x), "=f"(y) : "l"(v));
}
__device__ __forceinline__ void fma2(unsigned long long& d, unsigned long long a,
                                     unsigned long long b) {
    asm("fma.rn.f32x2 %0, %1, %2, %0;" : "+l"(d) : "l"(a), "l"(b));
}

// ------------------- fp16 table build -------------------
__global__ void k_tohalf(const float4* __restrict__ ue, const float4* __restrict__ ie) {
    int i = blockIdx.x * blockDim.x + threadIdx.x;  // over NTOT*16 float4
    if (i >= NTOT * (DEMB / 4)) return;
    float4 v = (i < N_USER * (DEMB / 4)) ? ue[i] : ie[i - N_USER * (DEMB / 4)];
    __half2 h01 = __floats2half2_rn(v.x, v.y);
    __half2 h23 = __floats2half2_rn(v.z, v.w);
    uint2 packed = make_uint2(*(unsigned*)&h01, *(unsigned*)&h23);
    *(uint2*)&g_E0h[(size_t)i * 4] = packed;
}

// ------------------- CSR build -------------------
__global__ void k_count(const int* __restrict__ rows) {
    int e = blockIdx.x * blockDim.x + threadIdx.x;
    if (e < NNZT) atomicAdd(&g_cnt[rows[e]], 1);
}

#define SCAN_NBLK 147

__global__ void k_scan1() {
    __shared__ int s[1024];
    int t = threadIdx.x;
    int i = blockIdx.x * 1024 + t;
    int x = (i <= NTOT) ? g_cnt[i] : 0;
    s[t] = x;
    __syncthreads();
    for (int d = 512; d > 0; d >>= 1) {
        if (t < d) s[t] += s[t + d];
        __syncthreads();
    }
    if (t == 0) g_part[blockIdx.x] = s[0];
}

__global__ void k_scan2() {
    if (threadIdx.x == 0 && blockIdx.x == 0) {
        int run = 0;
        for (int b = 0; b < SCAN_NBLK; b++) {
            int v = g_part[b];
            g_part[b] = run;
            run += v;
        }
    }
}

__global__ void k_scan3() {
    __shared__ int s[1024];
    int t = threadIdx.x;
    int i = blockIdx.x * 1024 + t;
    int x = (i <= NTOT) ? g_cnt[i] : 0;
    s[t] = x;
    __syncthreads();
    for (int d = 1; d < 1024; d <<= 1) {
        int v = (t >= d) ? s[t - d] : 0;
        __syncthreads();
        s[t] += v;
        __syncthreads();
    }
    int excl = g_part[blockIdx.x] + s[t] - x;
    if (i <= NTOT) {
        g_off[i] = excl;
        g_cur[i] = excl;
    }
}

__global__ void k_fill(const int* __restrict__ rows, const int* __restrict__ cols,
                       const float* __restrict__ vals) {
    int e = blockIdx.x * blockDim.x + threadIdx.x;
    if (e < NNZT) {
        int r = rows[e];
        int p = atomicAdd(&g_cur[r], 1);
        g_cv[p] = make_int2(cols[e], __float_as_int(vals[e]));
    }
}

// ------------------- SpMM gather (fp16 table, fp32 accum): AM = [LE+E | LE*E] -------------------
#define SW 16  // warps per block

__global__ __launch_bounds__(512) void k_spmm(int layer,
                                              const float* __restrict__ ue,
                                              const float* __restrict__ ie) {
    const __half* __restrict__ Eh = (layer == 0) ? g_E0h : g_Elayh[layer - 1];
    const float* __restrict__ Eprev = (layer == 0) ? (const float*)nullptr : g_Elay[layer - 1];
    int tid = threadIdx.x;
    int warp = tid >> 5, lane = tid & 31;
    int ngroups = (NTOT + SW - 1) / SW;

    for (int g = blockIdx.x; g < ngroups; g += gridDim.x) {
        int r = g * SW + warp;
        if (r >= NTOT) continue;
        int s = g_off[r], e2 = g_off[r + 1];
        float2 acc = make_float2(0.f, 0.f);
        for (int base = s; base < e2; base += 32) {
            int2 cv = make_int2(0, 0);
            if (base + lane < e2) cv = g_cv[base + lane];
            int cnt = min(32, e2 - base);
            int cnt8 = (cnt + 7) & ~7;
            for (int i = 0; i < cnt8; i += 8) {
#pragma unroll
                for (int u = 0; u < 8; u++) {
                    int cc = __shfl_sync(0xffffffffu, cv.x, i + u);
                    float vv = __int_as_float(__shfl_sync(0xffffffffu, cv.y, i + u));
                    __half2 xh = *(const __half2*)(Eh + (size_t)cc * DEMB + lane * 2);
                    float2 x = __half22float2(xh);
                    acc.x = fmaf(vv, x.x, acc.x);
                    acc.y = fmaf(vv, x.y, acc.y);
                }
            }
        }
        // residual in fp32 for accuracy (dominant term of a = LE + E)
        const float* rp0;
        if (layer == 0)
            rp0 = (r < N_USER) ? (ue + (size_t)r * DEMB)
                               : (ie + (size_t)(r - N_USER) * DEMB);
        else
            rp0 = Eprev + (size_t)r * DEMB;
        float2 e0 = *(const float2*)(rp0 + lane * 2);
        *(float2*)&g_AM[(size_t)r * 128 + lane * 2] =
            make_float2(acc.x + e0.x, acc.y + e0.y);
        *(float2*)&g_AM[(size_t)r * 128 + DEMB + lane * 2] =
            make_float2(acc.x * e0.x, acc.y * e0.y);
    }
}

// ------------------- tiled GEMM (FFMA2): leaky(AM @ [W1;W2] + b) + inv-norm + fp16 shadow -------------------
#define BM 128
#define BN 64
#define BK 16
#define PADA 4
#define PADB 4

__global__ __launch_bounds__(128) void k_gemm(int layer,
                                              const float* __restrict__ W1l,
                                              const float* __restrict__ W2l,
                                              const float* __restrict__ b1l,
                                              const float* __restrict__ b2l) {
    __shared__ __align__(16) float sA[BK][BM + PADA];
    __shared__ __align__(16) float sB[BK][BN + PADB];
    __shared__ float sBias[BN];

    float* __restrict__ Eout = g_Elay[layer];
    __half* __restrict__ Eouth = (layer < 2) ? g_Elayh[layer] : (__half*)nullptr;
    float* __restrict__ inorm = g_inorm[layer];

    int tid = threadIdx.x;
    int tx = tid & 7;    // 8 col-groups of 8
    int ty = tid >> 3;   // 16 row-groups of 8
    int m0 = blockIdx.x * BM;

    if (tid < BN) sBias[tid] = b1l[tid] + b2l[tid];

    unsigned long long acc2[8][4];  // [i][j-pair], each holds 2 fp32 accumulators
#pragma unroll
    for (int i = 0; i < 8; i++)
#pragma unroll
        for (int j = 0; j < 4; j++) acc2[i][j] = 0ull;

    for (int k0 = 0; k0 < 2 * DEMB; k0 += BK) {
        // A tile: rows m0..m0+127, cols k0..k0+15 -> sA[k][m] (transposed)
#pragma unroll
        for (int i = 0; i < 4; i++) {
            int idx = tid + i * 128;        // float4 index 0..511
            int m = idx >> 2;
            int kq = (idx & 3) * 4;
            float4 v = make_float4(0.f, 0.f, 0.f, 0.f);
            int gr = m0 + m;
            if (gr < NTOT) v = *(const float4*)&g_AM[(size_t)gr * 128 + k0 + kq];
            sA[kq + 0][m] = v.x;
            sA[kq + 1][m] = v.y;
            sA[kq + 2][m] = v.z;
            sA[kq + 3][m] = v.w;
        }
        // B tile: Wcat rows k0..k0+15 (W1 rows then W2 rows), cols 0..63
#pragma unroll
        for (int i = 0; i < 2; i++) {
            int idx = tid + i * 128;        // float4 index 0..255
            int kr = idx >> 4;
            int cq = (idx & 15) * 4;
            int gk = k0 + kr;
            const float* Wsrc = (gk < DEMB) ? (W1l + gk * DEMB) : (W2l + (gk - DEMB) * DEMB);
            *(float4*)&sB[kr][cq] = *(const float4*)&Wsrc[cq];
        }
        __syncthreads();
#pragma unroll
        for (int kk = 0; kk < BK; kk++) {
            float a[8], b[8];
            *(float4*)&a[0] = *(float4*)&sA[kk][ty * 8];
            *(float4*)&a[4] = *(float4*)&sA[kk][ty * 8 + 4];
            *(float4*)&b[0] = *(float4*)&sB[kk][tx * 8];
            *(float4*)&b[4] = *(float4*)&sB[kk][tx * 8 + 4];
            unsigned long long ap[8], bp[4];
#pragma unroll
            for (int i = 0; i < 8; i++) ap[i] = pack2(a[i], a[i]);
#pragma unroll
            for (int j = 0; j < 4; j++) bp[j] = pack2(b[2 * j], b[2 * j + 1]);
#pragma unroll
            for (int i = 0; i < 8; i++)
#pragma unroll
                for (int j = 0; j < 4; j++)
                    fma2(acc2[i][j], ap[i], bp[j]);
        }
        __syncthreads();
    }

    float bias[8];
    *(float4*)&bias[0] = *(float4*)&sBias[tx * 8];
    *(float4*)&bias[4] = *(float4*)&sBias[tx * 8 + 4];

#pragma unroll
    for (int i = 0; i < 8; i++) {
        int r = m0 + ty * 8 + i;
        float h[8];
        float ss = 0.f;
#pragma unroll
        for (int j = 0; j < 4; j++) {
            float v0, v1;
            unpack2(acc2[i][j], v0, v1);
            v0 += bias[2 * j];
            v1 += bias[2 * j + 1];
            v0 = v0 > 0.f ? v0 : NEG_SLOPE * v0;
            v1 = v1 > 0.f ? v1 : NEG_SLOPE * v1;
            h[2 * j] = v0;
            h[2 * j + 1] = v1;
            ss = fmaf(v0, v0, ss);
            ss = fmaf(v1, v1, ss);
        }
        ss += __shfl_xor_sync(0xffffffffu, ss, 1);
        ss += __shfl_xor_sync(0xffffffffu, ss, 2);
        ss += __shfl_xor_sync(0xffffffffu, ss, 4);
        if (r < NTOT) {
            *(float4*)&Eout[(size_t)r * DEMB + tx * 8] = *(float4*)&h[0];
            *(float4*)&Eout[(size_t)r * DEMB + tx * 8 + 4] = *(float4*)&h[4];
            if (Eouth) {
                __half2 hh0 = __floats2half2_rn(h[0], h[1]);
                __half2 hh1 = __floats2half2_rn(h[2], h[3]);
                __half2 hh2 = __floats2half2_rn(h[4], h[5]);
                __half2 hh3 = __floats2half2_rn(h[6], h[7]);
                uint4 packed = make_uint4(*(unsigned*)&hh0, *(unsigned*)&hh1,
                                          *(unsigned*)&hh2, *(unsigned*)&hh3);
                *(uint4*)&Eouth[(size_t)r * DEMB + tx * 8] = packed;
            }
            if (tx == 0) inorm[r] = 1.0f / fmaxf(sqrtf(ss), 1e-12f);
        }
    }
}

// ------------------- final gather -------------------
__global__ void k_gather(const int* __restrict__ users, const int* __restrict__ pos,
                         const int* __restrict__ neg, const float* __restrict__ ue,
                         const float* __restrict__ ie, float* __restrict__ out) {
    int b = blockIdx.x;
    int grp = b >> 12;
    int i = b & (BSZ - 1);
    int node;
    if (grp == 0) node = users[i] - 1;
    else if (grp == 1) node = N_USER + pos[i] - 1;
    else node = N_USER + neg[i] - 1;

    int j = threadIdx.x;  // 0..255
    int l = j >> 6, jj = j & 63;
    float v;
    if (l == 0) {
        v = (node < N_USER) ? ue[(size_t)node * DEMB + jj]
                            : ie[(size_t)(node - N_USER) * DEMB + jj];
    } else {
        v = g_Elay[l - 1][(size_t)node * DEMB + jj] * g_inorm[l - 1][node];
    }
    out[(size_t)b * 256 + j] = v;
}

// ------------------- launch -------------------
extern "C" void kernel_launch(void* const* d_in, const int* in_sizes, int n_in,
                              void* d_out, int out_size) {
    const float* ue = (const float*)d_in[0];
    const float* ie = (const float*)d_in[1];
    const float* ev = (const float*)d_in[2];
    const float* W1 = (const float*)d_in[3];
    const float* b1 = (const float*)d_in[4];
    const float* W2 = (const float*)d_in[5];
    const float* b2 = (const float*)d_in[6];
    const int* eidx = (const int*)d_in[7];
    const int* users = (const int*)d_in[8];
    const int* pos = (const int*)d_in[9];
    const int* neg = (const int*)d_in[10];
    float* out = (float*)d_out;

    const int* rows = eidx;
    const int* cols = eidx + NNZT;

    static void* p_cnt = nullptr;
    if (!p_cnt) cudaGetSymbolAddress(&p_cnt, g_cnt);

    cudaMemsetAsync(p_cnt, 0, (NTOT + 1) * sizeof(int));
    k_tohalf<<<(NTOT * (DEMB / 4) + 255) / 256, 256>>>((const float4*)ue, (const float4*)ie);
    k_count<<<(NNZT + 255) / 256, 256>>>(rows);
    k_scan1<<<SCAN_NBLK, 1024>>>();
    k_scan2<<<1, 32>>>();
    k_scan3<<<SCAN_NBLK, 1024>>>();
    k_fill<<<(NNZT + 255) / 256, 256>>>(rows, cols, ev);

    for (int l = 0; l < NLAYER; l++) {
        k_spmm<<<592, 512>>>(l, ue, ie);
        k_gemm<<<(NTOT + BM - 1) / BM, 128>>>(l, W1 + l * DEMB * DEMB, W2 + l * DEMB * DEMB,
                                              b1 + l * DEMB, b2 + l * DEMB);
    }
    k_gather<<<3 * BSZ, 256>>>(users, pos, neg, ue, ie, out);
}

// round 9
// speedup vs baseline: 1.7931x; 1.0139x over previous
#include <cuda_runtime.h>
#include <cuda_fp16.h>

#define N_USER 50000
#define N_ITEM 100000
#define NTOT   150000
#define DEMB   64
#define NNZT   2400000
#define BSZ    4096
#define NLAYER 3
#define NEG_SLOPE 0.2f

// ------------------- static device scratch -------------------
__device__ __align__(256) float  g_Elay[NLAYER][NTOT * DEMB];  // unnormalized fp32 layer outputs
__device__ __align__(256) __half g_E0h[NTOT * DEMB];           // fp16 concat(ue,ie) gather table
__device__ __align__(256) __half g_Elayh[2][NTOT * DEMB];      // fp16 shadow of layers 0,1
__device__ __align__(256) float  g_inorm[NLAYER][NTOT];        // 1/max(norm,eps)
__device__ __align__(256) float  g_AM[NTOT * 2 * DEMB];        // [a | m] GEMM operand
__device__ int  g_cnt[NTOT + 1];
__device__ int  g_off[NTOT + 1];
__device__ int  g_cur[NTOT + 1];
__device__ int2 g_cv[NNZT];                                    // packed (col, val-bits)
__device__ unsigned long long g_pub[160];                      // lookback publish words

// packed f32x2 helpers (Blackwell FFMA2 — PTX-only)
__device__ __forceinline__ unsigned long long pack2(float x, float y) {
    unsigned long long r;
    asm("mov.b64 %0, {%1, %2};" : "=l"(r) : "f"(x), "f"(y));
    return r;
}
__device__ __forceinline__ void unpack2(unsigned long long v, float& x, float& y) {
    asm("mov.b64 {%0, %1}, %2;" : "=f"(x), "=f"(y) : "l"(v));
}
__device__ __forceinline__ void fma2(unsigned long long& d, unsigned long long a,
                                     unsigned long long b) {
    asm("fma.rn.f32x2 %0, %1, %2, %0;" : "+l"(d) : "l"(a), "l"(b));
}

// ------------------- launch 1: fp16 table build + zero counters/pub -------------------
__global__ void k_tohalf(const float4* __restrict__ ue, const float4* __restrict__ ie) {
    int i = blockIdx.x * blockDim.x + threadIdx.x;  // over NTOT*16 float4
    if (i <= NTOT) g_cnt[i] = 0;
    if (i < 160) g_pub[i] = 0ull;
    if (i >= NTOT * (DEMB / 4)) return;
    float4 v = (i < N_USER * (DEMB / 4)) ? ue[i] : ie[i - N_USER * (DEMB / 4)];
    __half2 h01 = __floats2half2_rn(v.x, v.y);
    __half2 h23 = __floats2half2_rn(v.z, v.w);
    uint2 packed = make_uint2(*(unsigned*)&h01, *(unsigned*)&h23);
    *(uint2*)&g_E0h[(size_t)i * 4] = packed;
}

// ------------------- launch 2: histogram -------------------
__global__ void k_count(const int* __restrict__ rows) {
    int e = blockIdx.x * blockDim.x + threadIdx.x;
    if (e < NNZT) atomicAdd(&g_cnt[rows[e]], 1);
}

// ------------------- launch 3: single-kernel exclusive scan (parallel lookback) -------------------
#define SCAN_NBLK 147

__global__ __launch_bounds__(1024) void k_scan_one() {
    __shared__ int s[1024];
    __shared__ int s2[1024];
    int t = threadIdx.x;
    int b = blockIdx.x;
    int i = b * 1024 + t;
    int x = (i <= NTOT) ? g_cnt[i] : 0;
    s[t] = x;
    __syncthreads();
    // Hillis-Steele inclusive scan
#pragma unroll
    for (int d = 1; d < 1024; d <<= 1) {
        int v = (t >= d) ? s[t - d] : 0;
        __syncthreads();
        s[t] += v;
        __syncthreads();
    }
    // publish this block's aggregate (flag in bit 32)
    if (t == 0) {
        unsigned long long w = (1ull << 32) | (unsigned long long)(unsigned)s[1023];
        atomicExch(&g_pub[b], w);
    }
    // poll all predecessor aggregates in parallel
    int v = 0;
    if (t < b) {
        unsigned long long w;
        do {
            w = *(volatile unsigned long long*)&g_pub[t];
        } while (!(w >> 32));
        v = (int)(unsigned)w;
    }
    s2[t] = v;
    __syncthreads();
#pragma unroll
    for (int d = 512; d > 0; d >>= 1) {
        if (t < d) s2[t] += s2[t + d];
        __syncthreads();
    }
    int prefix = s2[0];
    int excl = prefix + s[t] - x;
    if (i <= NTOT) {
        g_off[i] = excl;
        g_cur[i] = excl;
    }
}

// ------------------- launch 4: CSR fill -------------------
__global__ void k_fill(const int* __restrict__ rows, const int* __restrict__ cols,
                       const float* __restrict__ vals) {
    int e = blockIdx.x * blockDim.x + threadIdx.x;
    if (e < NNZT) {
        int r = rows[e];
        int p = atomicAdd(&g_cur[r], 1);
        g_cv[p] = make_int2(cols[e], __float_as_int(vals[e]));
    }
}

// ------------------- SpMM gather (fp16 table, fp32 accum): AM = [LE+E | LE*E] -------------------
#define SW 16  // warps per block

__global__ __launch_bounds__(512) void k_spmm(int layer,
                                              const float* __restrict__ ue,
                                              const float* __restrict__ ie) {
    const __half* __restrict__ Eh = (layer == 0) ? g_E0h : g_Elayh[layer - 1];
    const float* __restrict__ Eprev = (layer == 0) ? (const float*)nullptr : g_Elay[layer - 1];
    int tid = threadIdx.x;
    int warp = tid >> 5, lane = tid & 31;
    int ngroups = (NTOT + SW - 1) / SW;

    for (int g = blockIdx.x; g < ngroups; g += gridDim.x) {
        int r = g * SW + warp;
        if (r >= NTOT) continue;
        int s = g_off[r], e2 = g_off[r + 1];
        float2 acc = make_float2(0.f, 0.f);
        for (int base = s; base < e2; base += 32) {
            int2 cv = make_int2(0, 0);
            if (base + lane < e2) cv = g_cv[base + lane];
            int cnt = min(32, e2 - base);
            int cnt8 = (cnt + 7) & ~7;
            for (int i = 0; i < cnt8; i += 8) {
#pragma unroll
                for (int u = 0; u < 8; u++) {
                    int cc = __shfl_sync(0xffffffffu, cv.x, i + u);
                    float vv = __int_as_float(__shfl_sync(0xffffffffu, cv.y, i + u));
                    __half2 xh = *(const __half2*)(Eh + (size_t)cc * DEMB + lane * 2);
                    float2 x = __half22float2(xh);
                    acc.x = fmaf(vv, x.x, acc.x);
                    acc.y = fmaf(vv, x.y, acc.y);
                }
            }
        }
        // residual in fp32 for accuracy (dominant term of a = LE + E)
        const float* rp0;
        if (layer == 0)
            rp0 = (r < N_USER) ? (ue + (size_t)r * DEMB)
                               : (ie + (size_t)(r - N_USER) * DEMB);
        else
            rp0 = Eprev + (size_t)r * DEMB;
        float2 e0 = *(const float2*)(rp0 + lane * 2);
        *(float2*)&g_AM[(size_t)r * 128 + lane * 2] =
            make_float2(acc.x + e0.x, acc.y + e0.y);
        *(float2*)&g_AM[(size_t)r * 128 + DEMB + lane * 2] =
            make_float2(acc.x * e0.x, acc.y * e0.y);
    }
}

// ------------------- tiled GEMM (FFMA2): leaky(AM @ [W1;W2] + b) + inv-norm + fp16 shadow -------------------
#define BM 128
#define BN 64
#define BK 16
#define PADA 4
#define PADB 4

__global__ __launch_bounds__(128) void k_gemm(int layer,
                                              const float* __restrict__ W1l,
                                              const float* __restrict__ W2l,
                                              const float* __restrict__ b1l,
                                              const float* __restrict__ b2l) {
    __shared__ __align__(16) float sA[BK][BM + PADA];
    __shared__ __align__(16) float sB[BK][BN + PADB];
    __shared__ float sBias[BN];

    float* __restrict__ Eout = g_Elay[layer];
    __half* __restrict__ Eouth = (layer < 2) ? g_Elayh[layer] : (__half*)nullptr;
    float* __restrict__ inorm = g_inorm[layer];

    int tid = threadIdx.x;
    int tx = tid & 7;    // 8 col-groups of 8
    int ty = tid >> 3;   // 16 row-groups of 8
    int m0 = blockIdx.x * BM;

    if (tid < BN) sBias[tid] = b1l[tid] + b2l[tid];

    unsigned long long acc2[8][4];  // [i][j-pair], each holds 2 fp32 accumulators
#pragma unroll
    for (int i = 0; i < 8; i++)
#pragma unroll
        for (int j = 0; j < 4; j++) acc2[i][j] = 0ull;

    for (int k0 = 0; k0 < 2 * DEMB; k0 += BK) {
        // A tile: rows m0..m0+127, cols k0..k0+15 -> sA[k][m] (transposed)
#pragma unroll
        for (int i = 0; i < 4; i++) {
            int idx = tid + i * 128;        // float4 index 0..511
            int m = idx >> 2;
            int kq = (idx & 3) * 4;
            float4 v = make_float4(0.f, 0.f, 0.f, 0.f);
            int gr = m0 + m;
            if (gr < NTOT) v = *(const float4*)&g_AM[(size_t)gr * 128 + k0 + kq];
            sA[kq + 0][m] = v.x;
            sA[kq + 1][m] = v.y;
            sA[kq + 2][m] = v.z;
            sA[kq + 3][m] = v.w;
        }
        // B tile: Wcat rows k0..k0+15 (W1 rows then W2 rows), cols 0..63
#pragma unroll
        for (int i = 0; i < 2; i++) {
            int idx = tid + i * 128;        // float4 index 0..255
            int kr = idx >> 4;
            int cq = (idx & 15) * 4;
            int gk = k0 + kr;
            const float* Wsrc = (gk < DEMB) ? (W1l + gk * DEMB) : (W2l + (gk - DEMB) * DEMB);
            *(float4*)&sB[kr][cq] = *(const float4*)&Wsrc[cq];
        }
        __syncthreads();
#pragma unroll
        for (int kk = 0; kk < BK; kk++) {
            float a[8], b[8];
            *(float4*)&a[0] = *(float4*)&sA[kk][ty * 8];
            *(float4*)&a[4] = *(float4*)&sA[kk][ty * 8 + 4];
            *(float4*)&b[0] = *(float4*)&sB[kk][tx * 8];
            *(float4*)&b[4] = *(float4*)&sB[kk][tx * 8 + 4];
            unsigned long long ap[8], bp[4];
#pragma unroll
            for (int i = 0; i < 8; i++) ap[i] = pack2(a[i], a[i]);
#pragma unroll
            for (int j = 0; j < 4; j++) bp[j] = pack2(b[2 * j], b[2 * j + 1]);
#pragma unroll
            for (int i = 0; i < 8; i++)
#pragma unroll
                for (int j = 0; j < 4; j++)
                    fma2(acc2[i][j], ap[i], bp[j]);
        }
        __syncthreads();
    }

    float bias[8];
    *(float4*)&bias[0] = *(float4*)&sBias[tx * 8];
    *(float4*)&bias[4] = *(float4*)&sBias[tx * 8 + 4];

#pragma unroll
    for (int i = 0; i < 8; i++) {
        int r = m0 + ty * 8 + i;
        float h[8];
        float ss = 0.f;
#pragma unroll
        for (int j = 0; j < 4; j++) {
            float v0, v1;
            unpack2(acc2[i][j], v0, v1);
            v0 += bias[2 * j];
            v1 += bias[2 * j + 1];
            v0 = v0 > 0.f ? v0 : NEG_SLOPE * v0;
            v1 = v1 > 0.f ? v1 : NEG_SLOPE * v1;
            h[2 * j] = v0;
            h[2 * j + 1] = v1;
            ss = fmaf(v0, v0, ss);
            ss = fmaf(v1, v1, ss);
        }
        ss += __shfl_xor_sync(0xffffffffu, ss, 1);
        ss += __shfl_xor_sync(0xffffffffu, ss, 2);
        ss += __shfl_xor_sync(0xffffffffu, ss, 4);
        if (r < NTOT) {
            *(float4*)&Eout[(size_t)r * DEMB + tx * 8] = *(float4*)&h[0];
            *(float4*)&Eout[(size_t)r * DEMB + tx * 8 + 4] = *(float4*)&h[4];
            if (Eouth) {
                __half2 hh0 = __floats2half2_rn(h[0], h[1]);
                __half2 hh1 = __floats2half2_rn(h[2], h[3]);
                __half2 hh2 = __floats2half2_rn(h[4], h[5]);
                __half2 hh3 = __floats2half2_rn(h[6], h[7]);
                uint4 packed = make_uint4(*(unsigned*)&hh0, *(unsigned*)&hh1,
                                          *(unsigned*)&hh2, *(unsigned*)&hh3);
                *(uint4*)&Eouth[(size_t)r * DEMB + tx * 8] = packed;
            }
            if (tx == 0) inorm[r] = 1.0f / fmaxf(sqrtf(ss), 1e-12f);
        }
    }
}

// ------------------- final gather -------------------
__global__ void k_gather(const int* __restrict__ users, const int* __restrict__ pos,
                         const int* __restrict__ neg, const float* __restrict__ ue,
                         const float* __restrict__ ie, float* __restrict__ out) {
    int b = blockIdx.x;
    int grp = b >> 12;
    int i = b & (BSZ - 1);
    int node;
    if (grp == 0) node = users[i] - 1;
    else if (grp == 1) node = N_USER + pos[i] - 1;
    else node = N_USER + neg[i] - 1;

    int j = threadIdx.x;  // 0..255
    int l = j >> 6, jj = j & 63;
    float v;
    if (l == 0) {
        v = (node < N_USER) ? ue[(size_t)node * DEMB + jj]
                            : ie[(size_t)(node - N_USER) * DEMB + jj];
    } else {
        v = g_Elay[l - 1][(size_t)node * DEMB + jj] * g_inorm[l - 1][node];
    }
    out[(size_t)b * 256 + j] = v;
}

// ------------------- launch -------------------
extern "C" void kernel_launch(void* const* d_in, const int* in_sizes, int n_in,
                              void* d_out, int out_size) {
    const float* ue = (const float*)d_in[0];
    const float* ie = (const float*)d_in[1];
    const float* ev = (const float*)d_in[2];
    const float* W1 = (const float*)d_in[3];
    const float* b1 = (const float*)d_in[4];
    const float* W2 = (const float*)d_in[5];
    const float* b2 = (const float*)d_in[6];
    const int* eidx = (const int*)d_in[7];
    const int* users = (const int*)d_in[8];
    const int* pos = (const int*)d_in[9];
    const int* neg = (const int*)d_in[10];
    float* out = (float*)d_out;

    const int* rows = eidx;
    const int* cols = eidx + NNZT;

    // launch 1: fp16 table + zero cnt/pub
    k_tohalf<<<(NTOT * (DEMB / 4) + 255) / 256, 256>>>((const float4*)ue, (const float4*)ie);
    // launch 2: histogram
    k_count<<<(NNZT + 255) / 256, 256>>>(rows);
    // launch 3: one-kernel scan
    k_scan_one<<<SCAN_NBLK, 1024>>>();
    // launch 4: fill
    k_fill<<<(NNZT + 255) / 256, 256>>>(rows, cols, ev);

    // launch 5 = spmm(layer 0)  <-- ncu capture target
    for (int l = 0; l < NLAYER; l++) {
        k_spmm<<<592, 512>>>(l, ue, ie);
        k_gemm<<<(NTOT + BM - 1) / BM, 128>>>(l, W1 + l * DEMB * DEMB, W2 + l * DEMB * DEMB,
                                              b1 + l * DEMB, b2 + l * DEMB);
    }
    k_gather<<<3 * BSZ, 256>>>(users, pos, neg, ue, ie, out);
}

// round 10
// speedup vs baseline: 1.7934x; 1.0001x over previous
#include <cuda_runtime.h>
#include <cuda_fp16.h>

#define N_USER 50000
#define N_ITEM 100000
#define NTOT   150000
#define DEMB   64
#define NNZT   2400000
#define BSZ    4096
#define NLAYER 3
#define NEG_SLOPE 0.2f

// ------------------- static device scratch -------------------
__device__ __align__(256) float  g_Elay[NLAYER][NTOT * DEMB];  // unnormalized fp32 layer outputs
__device__ __align__(256) __half g_E0h[NTOT * DEMB];           // fp16 concat(ue,ie) gather table
__device__ __align__(256) __half g_Elayh[2][NTOT * DEMB];      // fp16 shadow of layers 0,1
__device__ __align__(256) float  g_inorm[NLAYER][NTOT];        // 1/max(norm,eps)
__device__ __align__(256) float  g_AM[NTOT * 2 * DEMB];        // [a | m] GEMM operand
__device__ int  g_cnt[NTOT + 1];
__device__ int  g_off[NTOT + 1];
__device__ int  g_cur[NTOT + 1];
__device__ int2 g_cv[NNZT];                                    // packed (col, val-bits)
__device__ unsigned long long g_pub[160];                      // lookback publish words

// packed f32x2 helpers (Blackwell FFMA2 — PTX-only)
__device__ __forceinline__ unsigned long long pack2(float x, float y) {
    unsigned long long r;
    asm("mov.b64 %0, {%1, %2};" : "=l"(r) : "f"(x), "f"(y));
    return r;
}
__device__ __forceinline__ void unpack2(unsigned long long v, float& x, float& y) {
    asm("mov.b64 {%0, %1}, %2;" : "=f"(x), "=f"(y) : "l"(v));
}
__device__ __forceinline__ void fma2(unsigned long long& d, unsigned long long a,
                                     unsigned long long b) {
    asm("fma.rn.f32x2 %0, %1, %2, %0;" : "+l"(d) : "l"(a), "l"(b));
}

// ------------------- kernel 1: fp16 table build + row histogram -------------------
__global__ void k_prep(const float4* __restrict__ ue, const float4* __restrict__ ie,
                       const int* __restrict__ rows) {
    int i = blockIdx.x * blockDim.x + threadIdx.x;  // 0 .. NNZT-1
    if (i < NNZT) atomicAdd(&g_cnt[rows[i]], 1);
    if (i < NTOT * (DEMB / 4)) {
        float4 v = (i < N_USER * (DEMB / 4)) ? ue[i] : ie[i - N_USER * (DEMB / 4)];
        __half2 h01 = __floats2half2_rn(v.x, v.y);
        __half2 h23 = __floats2half2_rn(v.z, v.w);
        uint2 packed = make_uint2(*(unsigned*)&h01, *(unsigned*)&h23);
        *(uint2*)&g_E0h[(size_t)i * 4] = packed;
    }
}

// ------------------- kernel 2: single-kernel exclusive scan (parallel lookback) -------------------
#define SCAN_NBLK 147

__global__ __launch_bounds__(1024) void k_scan_one() {
    __shared__ int s[1024];
    __shared__ int s2[1024];
    int t = threadIdx.x;
    int b = blockIdx.x;
    int i = b * 1024 + t;
    int x = (i <= NTOT) ? g_cnt[i] : 0;
    s[t] = x;
    __syncthreads();
#pragma unroll
    for (int d = 1; d < 1024; d <<= 1) {
        int v = (t >= d) ? s[t - d] : 0;
        __syncthreads();
        s[t] += v;
        __syncthreads();
    }
    if (t == 0) {
        unsigned long long w = (1ull << 32) | (unsigned long long)(unsigned)s[1023];
        atomicExch(&g_pub[b], w);
    }
    int v = 0;
    if (t < b) {
        unsigned long long w;
        do {
            w = *(volatile unsigned long long*)&g_pub[t];
        } while (!(w >> 32));
        v = (int)(unsigned)w;
    }
    s2[t] = v;
    __syncthreads();
#pragma unroll
    for (int d = 512; d > 0; d >>= 1) {
        if (t < d) s2[t] += s2[t + d];
        __syncthreads();
    }
    int prefix = s2[0];
    int excl = prefix + s[t] - x;
    if (i <= NTOT) {
        g_off[i] = excl;
        g_cur[i] = excl;
    }
}

// ------------------- kernel 3: CSR fill -------------------
__global__ void k_fill(const int* __restrict__ rows, const int* __restrict__ cols,
                       const float* __restrict__ vals) {
    int e = blockIdx.x * blockDim.x + threadIdx.x;
    if (e < NNZT) {
        int r = rows[e];
        int p = atomicAdd(&g_cur[r], 1);
        g_cv[p] = make_int2(cols[e], __float_as_int(vals[e]));
    }
}

// ------------------- kernel 4 (profiled): SpMM gather, AM = [LE+E | LE*E] -------------------
#define SW 16  // warps per block

__global__ __launch_bounds__(512) void k_spmm(int layer,
                                              const float* __restrict__ ue,
                                              const float* __restrict__ ie) {
    const __half* __restrict__ Eh = (layer == 0) ? g_E0h : g_Elayh[layer - 1];
    const float* __restrict__ Eprev = (layer == 0) ? (const float*)nullptr : g_Elay[layer - 1];
    int tid = threadIdx.x;
    int warp = tid >> 5, lane = tid & 31;
    int ngroups = (NTOT + SW - 1) / SW;

    for (int g = blockIdx.x; g < ngroups; g += gridDim.x) {
        int r = g * SW + warp;
        if (r >= NTOT) continue;
        int s = g_off[r], e2 = g_off[r + 1];
        float2 acc = make_float2(0.f, 0.f);
        for (int base = s; base < e2; base += 32) {
            int2 cv = make_int2(0, 0);
            if (base + lane < e2) cv = g_cv[base + lane];
            int cnt = min(32, e2 - base);
            int cnt8 = (cnt + 7) & ~7;
            for (int i = 0; i < cnt8; i += 8) {
#pragma unroll
                for (int u = 0; u < 8; u++) {
                    int cc = __shfl_sync(0xffffffffu, cv.x, i + u);
                    float vv = __int_as_float(__shfl_sync(0xffffffffu, cv.y, i + u));
                    __half2 xh = *(const __half2*)(Eh + (size_t)cc * DEMB + lane * 2);
                    float2 x = __half22float2(xh);
                    acc.x = fmaf(vv, x.x, acc.x);
                    acc.y = fmaf(vv, x.y, acc.y);
                }
            }
        }
        const float* rp0;
        if (layer == 0)
            rp0 = (r < N_USER) ? (ue + (size_t)r * DEMB)
                               : (ie + (size_t)(r - N_USER) * DEMB);
        else
            rp0 = Eprev + (size_t)r * DEMB;
        float2 e0 = *(const float2*)(rp0 + lane * 2);
        *(float2*)&g_AM[(size_t)r * 128 + lane * 2] =
            make_float2(acc.x + e0.x, acc.y + e0.y);
        *(float2*)&g_AM[(size_t)r * 128 + DEMB + lane * 2] =
            make_float2(acc.x * e0.x, acc.y * e0.y);
    }
}

// ------------------- tiled GEMM (FFMA2): leaky(AM @ [W1;W2] + b) + inv-norm + fp16 shadow -------------------
#define BM 128
#define BN 64
#define BK 16
#define PADA 4
#define PADB 4

__global__ __launch_bounds__(128) void k_gemm(int layer,
                                              const float* __restrict__ W1l,
                                              const float* __restrict__ W2l,
                                              const float* __restrict__ b1l,
                                              const float* __restrict__ b2l) {
    __shared__ __align__(16) float sA[BK][BM + PADA];
    __shared__ __align__(16) float sB[BK][BN + PADB];
    __shared__ float sBias[BN];

    float* __restrict__ Eout = g_Elay[layer];
    __half* __restrict__ Eouth = (layer < 2) ? g_Elayh[layer] : (__half*)nullptr;
    float* __restrict__ inorm = g_inorm[layer];

    int tid = threadIdx.x;
    int tx = tid & 7;    // 8 col-groups of 8
    int ty = tid >> 3;   // 16 row-groups of 8
    int m0 = blockIdx.x * BM;

    if (tid < BN) sBias[tid] = b1l[tid] + b2l[tid];

    unsigned long long acc2[8][4];  // [i][j-pair], each holds 2 fp32 accumulators
#pragma unroll
    for (int i = 0; i < 8; i++)
#pragma unroll
        for (int j = 0; j < 4; j++) acc2[i][j] = 0ull;

    for (int k0 = 0; k0 < 2 * DEMB; k0 += BK) {
#pragma unroll
        for (int i = 0; i < 4; i++) {
            int idx = tid + i * 128;        // float4 index 0..511
            int m = idx >> 2;
            int kq = (idx & 3) * 4;
            float4 v = make_float4(0.f, 0.f, 0.f, 0.f);
            int gr = m0 + m;
            if (gr < NTOT) v = *(const float4*)&g_AM[(size_t)gr * 128 + k0 + kq];
            sA[kq + 0][m] = v.x;
            sA[kq + 1][m] = v.y;
            sA[kq + 2][m] = v.z;
            sA[kq + 3][m] = v.w;
        }
#pragma unroll
        for (int i = 0; i < 2; i++) {
            int idx = tid + i * 128;        // float4 index 0..255
            int kr = idx >> 4;
            int cq = (idx & 15) * 4;
            int gk = k0 + kr;
            const float* Wsrc = (gk < DEMB) ? (W1l + gk * DEMB) : (W2l + (gk - DEMB) * DEMB);
            *(float4*)&sB[kr][cq] = *(const float4*)&Wsrc[cq];
        }
        __syncthreads();
#pragma unroll
        for (int kk = 0; kk < BK; kk++) {
            float a[8], b[8];
            *(float4*)&a[0] = *(float4*)&sA[kk][ty * 8];
            *(float4*)&a[4] = *(float4*)&sA[kk][ty * 8 + 4];
            *(float4*)&b[0] = *(float4*)&sB[kk][tx * 8];
            *(float4*)&b[4] = *(float4*)&sB[kk][tx * 8 + 4];
            unsigned long long ap[8], bp[4];
#pragma unroll
            for (int i = 0; i < 8; i++) ap[i] = pack2(a[i], a[i]);
#pragma unroll
            for (int j = 0; j < 4; j++) bp[j] = pack2(b[2 * j], b[2 * j + 1]);
#pragma unroll
            for (int i = 0; i < 8; i++)
#pragma unroll
                for (int j = 0; j < 4; j++)
                    fma2(acc2[i][j], ap[i], bp[j]);
        }
        __syncthreads();
    }

    float bias[8];
    *(float4*)&bias[0] = *(float4*)&sBias[tx * 8];
    *(float4*)&bias[4] = *(float4*)&sBias[tx * 8 + 4];

#pragma unroll
    for (int i = 0; i < 8; i++) {
        int r = m0 + ty * 8 + i;
        float h[8];
        float ss = 0.f;
#pragma unroll
        for (int j = 0; j < 4; j++) {
            float v0, v1;
            unpack2(acc2[i][j], v0, v1);
            v0 += bias[2 * j];
            v1 += bias[2 * j + 1];
            v0 = v0 > 0.f ? v0 : NEG_SLOPE * v0;
            v1 = v1 > 0.f ? v1 : NEG_SLOPE * v1;
            h[2 * j] = v0;
            h[2 * j + 1] = v1;
            ss = fmaf(v0, v0, ss);
            ss = fmaf(v1, v1, ss);
        }
        ss += __shfl_xor_sync(0xffffffffu, ss, 1);
        ss += __shfl_xor_sync(0xffffffffu, ss, 2);
        ss += __shfl_xor_sync(0xffffffffu, ss, 4);
        if (r < NTOT) {
            *(float4*)&Eout[(size_t)r * DEMB + tx * 8] = *(float4*)&h[0];
            *(float4*)&Eout[(size_t)r * DEMB + tx * 8 + 4] = *(float4*)&h[4];
            if (Eouth) {
                __half2 hh0 = __floats2half2_rn(h[0], h[1]);
                __half2 hh1 = __floats2half2_rn(h[2], h[3]);
                __half2 hh2 = __floats2half2_rn(h[4], h[5]);
                __half2 hh3 = __floats2half2_rn(h[6], h[7]);
                uint4 packed = make_uint4(*(unsigned*)&hh0, *(unsigned*)&hh1,
                                          *(unsigned*)&hh2, *(unsigned*)&hh3);
                *(uint4*)&Eouth[(size_t)r * DEMB + tx * 8] = packed;
            }
            if (tx == 0) inorm[r] = 1.0f / fmaxf(sqrtf(ss), 1e-12f);
        }
    }
}

// ------------------- final gather -------------------
__global__ void k_gather(const int* __restrict__ users, const int* __restrict__ pos,
                         const int* __restrict__ neg, const float* __restrict__ ue,
                         const float* __restrict__ ie, float* __restrict__ out) {
    int b = blockIdx.x;
    int grp = b >> 12;
    int i = b & (BSZ - 1);
    int node;
    if (grp == 0) node = users[i] - 1;
    else if (grp == 1) node = N_USER + pos[i] - 1;
    else node = N_USER + neg[i] - 1;

    int j = threadIdx.x;  // 0..255
    int l = j >> 6, jj = j & 63;
    float v;
    if (l == 0) {
        v = (node < N_USER) ? ue[(size_t)node * DEMB + jj]
                            : ie[(size_t)(node - N_USER) * DEMB + jj];
    } else {
        v = g_Elay[l - 1][(size_t)node * DEMB + jj] * g_inorm[l - 1][node];
    }
    out[(size_t)b * 256 + j] = v;
}

// ------------------- launch -------------------
extern "C" void kernel_launch(void* const* d_in, const int* in_sizes, int n_in,
                              void* d_out, int out_size) {
    const float* ue = (const float*)d_in[0];
    const float* ie = (const float*)d_in[1];
    const float* ev = (const float*)d_in[2];
    const float* W1 = (const float*)d_in[3];
    const float* b1 = (const float*)d_in[4];
    const float* W2 = (const float*)d_in[5];
    const float* b2 = (const float*)d_in[6];
    const int* eidx = (const int*)d_in[7];
    const int* users = (const int*)d_in[8];
    const int* pos = (const int*)d_in[9];
    const int* neg = (const int*)d_in[10];
    float* out = (float*)d_out;

    const int* rows = eidx;
    const int* cols = eidx + NNZT;

    static void* p_cnt = nullptr;
    static void* p_pub = nullptr;
    if (!p_cnt) {
        cudaGetSymbolAddress(&p_cnt, g_cnt);
        cudaGetSymbolAddress(&p_pub, g_pub);
    }

    // memsets: not counted as kernel launches by the profiler
    cudaMemsetAsync(p_cnt, 0, (NTOT + 1) * sizeof(int));
    cudaMemsetAsync(p_pub, 0, 160 * sizeof(unsigned long long));

    // kernel 1: fp16 table + histogram (merged)
    k_prep<<<(NNZT + 255) / 256, 256>>>((const float4*)ue, (const float4*)ie, rows);
    // kernel 2: one-kernel scan
    k_scan_one<<<SCAN_NBLK, 1024>>>();
    // kernel 3: fill
    k_fill<<<(NNZT + 255) / 256, 256>>>(rows, cols, ev);

    // kernel 4 = spmm(layer 0)  <-- ncu capture target
    for (int l = 0; l < NLAYER; l++) {
        k_spmm<<<592, 512>>>(l, ue, ie);
        k_gemm<<<(NTOT + BM - 1) / BM, 128>>>(l, W1 + l * DEMB * DEMB, W2 + l * DEMB * DEMB,
                                              b1 + l * DEMB, b2 + l * DEMB);
    }
    k_gather<<<3 * BSZ, 256>>>(users, pos, neg, ue, ie, out);
}